// round 1
// baseline (speedup 1.0000x reference)
#include <cuda_runtime.h>
#include <math.h>

#define NN 100000
#define NE 1600000
#define NC 2000
#define NF 64
#define EFD 41
#define KD 169          // 2*64+41
#define HD 128
#define NCONV 3
#define TE 64           // edges per tile
#define ZLD 172         // padded z row length
#define BN_EPS 1e-5f

// ---------------- scratch (static device memory; no allocs) ----------------
static __device__ float g_x[(size_t)NN * NF];          // node features
static __device__ float g_y[(size_t)NE * HD];          // pre-BN edge activations (819MB)
static __device__ float g_nodeacc[(size_t)NN * NF];    // message accumulator
static __device__ float g_crys[(size_t)NC * NF];       // crystal accumulator
static __device__ float g_stats[256];                  // edge BN: sum[128] | sumsq[128]
static __device__ float g_nstats[128];                 // node BN: sum[64] | sumsq[64]
static __device__ float g_escale[128];
static __device__ float g_eshift[128];
static __device__ float g_nscale[64];
static __device__ float g_nshift[64];
static __device__ int   g_cnt1[NN];
static __device__ float g_inv1[NN];
static __device__ int   g_cntc[NC];
static __device__ float g_invc[NC];

// ---------------- helpers ----------------
__device__ __forceinline__ float spf(float x) {        // softplus, jax-stable
    return (x > 20.f) ? x : log1pf(expf(x));
}
__device__ __forceinline__ float sigf(float x) {
    return 1.f / (1.f + expf(-x));
}
__device__ __forceinline__ void red4(float* p, float4 v) {
    asm volatile("red.global.add.v4.f32 [%0], {%1,%2,%3,%4};"
                 :: "l"(p), "f"(v.x), "f"(v.y), "f"(v.z), "f"(v.w) : "memory");
}

// ---------------- setup kernels ----------------
__global__ void k_count_edges(const int* __restrict__ idx1) {
    int i = blockIdx.x * blockDim.x + threadIdx.x;
    if (i < NE) atomicAdd(&g_cnt1[idx1[i]], 1);
}
__global__ void k_count_crys(const int* __restrict__ idx3) {
    int i = blockIdx.x * blockDim.x + threadIdx.x;
    if (i < NN) atomicAdd(&g_cntc[idx3[i]], 1);
}
__global__ void k_inv() {
    int i = blockIdx.x * blockDim.x + threadIdx.x;
    if (i < NN) g_inv1[i] = 1.f / (float)max(g_cnt1[i], 1);
    if (i < NC) g_invc[i] = 1.f / (float)max(g_cntc[i], 1);
}
__global__ void k_embed(const int* __restrict__ node_fea, const float* __restrict__ emb) {
    int i = blockIdx.x * blockDim.x + threadIdx.x;   // over NN*16 float4s
    if (i >= NN * 16) return;
    int n = i >> 4, q = i & 15;
    int nf = node_fea[n];
    ((float4*)g_x)[i] = ((const float4*)emb)[nf * 16 + q];
}

// ---------------- pass A: z@W+b -> g_y, accumulate col sum/sumsq ----------------
__global__ void __launch_bounds__(256, 1)
k_passA(const float* __restrict__ ef, const int* __restrict__ idx1,
        const int* __restrict__ idx2, const float* __restrict__ W,
        const float* __restrict__ b) {
    extern __shared__ float sm[];
    float* sW   = sm;                        // 169*128
    float* sB   = sW + KD * HD;              // 128
    float* szs  = sB + HD;                   // 64*172
    int*   sI1  = (int*)(szs + TE * ZLD);    // 64
    int*   sI2  = sI1 + TE;                  // 64
    float* sred = (float*)(sI2 + TE);        // 256

    const int tid = threadIdx.x;
    for (int i = tid; i < KD * HD; i += 256) sW[i] = W[i];
    if (tid < HD) sB[tid] = b[tid];
    sred[tid] = 0.f;

    const int tx = tid & 31;   // 32 col groups of 4
    const int ty = tid >> 5;   // 8 edge groups of 8
    float csum[4] = {0.f, 0.f, 0.f, 0.f};
    float csq[4]  = {0.f, 0.f, 0.f, 0.f};

    const int nTiles = NE / TE;   // 25000 exact
    for (int t = blockIdx.x; t < nTiles; t += gridDim.x) {
        const int e0 = t * TE;
        __syncthreads();                       // protect szs from prior readers
        if (tid < TE) { sI1[tid] = idx1[e0 + tid]; sI2[tid] = idx2[e0 + tid]; }
        __syncthreads();
        // gather x[idx1] | x[idx2] (float4)
        #pragma unroll
        for (int it = 0; it < 8; ++it) {
            int i = tid + it * 256;            // < 2048 = 64*32
            int e = i >> 5, q = i & 31;
            const float4* src = (q < 16)
                ? ((const float4*)(g_x + (size_t)sI1[e] * NF)) + q
                : ((const float4*)(g_x + (size_t)sI2[e] * NF)) + (q - 16);
            *(float4*)(szs + e * ZLD + q * 4) = *src;
        }
        // edge features (coalesced scalar)
        #pragma unroll
        for (int it = 0; it < 11; ++it) {
            int i = tid + it * 256;
            if (i < TE * EFD) {
                int e = i / EFD, r = i - e * EFD;
                szs[e * ZLD + 128 + r] = ef[(size_t)(e0 + e) * EFD + r];
            }
        }
        __syncthreads();

        float acc[8][4];
        #pragma unroll
        for (int i = 0; i < 8; i++)
            #pragma unroll
            for (int j = 0; j < 4; j++) acc[i][j] = 0.f;

        const float*  zr = szs + (ty * 8) * ZLD;
        const float4* w4 = ((const float4*)sW) + tx;
        #pragma unroll 4
        for (int k = 0; k < KD; ++k) {
            float4 w = w4[k * 32];
            #pragma unroll
            for (int i = 0; i < 8; i++) {
                float z = zr[i * ZLD + k];
                acc[i][0] += z * w.x; acc[i][1] += z * w.y;
                acc[i][2] += z * w.z; acc[i][3] += z * w.w;
            }
        }
        float4 bb = *(((const float4*)sB) + tx);
        #pragma unroll
        for (int i = 0; i < 8; i++) {
            float4 v;
            v.x = acc[i][0] + bb.x; v.y = acc[i][1] + bb.y;
            v.z = acc[i][2] + bb.z; v.w = acc[i][3] + bb.w;
            csum[0] += v.x; csum[1] += v.y; csum[2] += v.z; csum[3] += v.w;
            csq[0] += v.x * v.x; csq[1] += v.y * v.y;
            csq[2] += v.z * v.z; csq[3] += v.w * v.w;
            *(float4*)(g_y + (size_t)(e0 + ty * 8 + i) * HD + tx * 4) = v;
        }
    }
    __syncthreads();
    #pragma unroll
    for (int j = 0; j < 4; j++) {
        atomicAdd(&sred[tx * 4 + j], csum[j]);
        atomicAdd(&sred[128 + tx * 4 + j], csq[j]);
    }
    __syncthreads();
    atomicAdd(&g_stats[tid], sred[tid]);
}

__global__ void k_fin_edge(const float* __restrict__ g1, const float* __restrict__ be1) {
    int j = threadIdx.x;            // 128
    float m  = g_stats[j] * (1.f / (float)NE);
    float sq = g_stats[128 + j] * (1.f / (float)NE);
    float rstd = rsqrtf(sq - m * m + BN_EPS);
    float sc = g1[j] * rstd;
    g_escale[j] = sc;
    g_eshift[j] = be1[j] - m * sc;
}

// ---------------- pass B: normalize, gate*softplus, scatter ----------------
__global__ void __launch_bounds__(256)
k_passB(const int* __restrict__ idx1) {
    __shared__ float ssc[128], ssh[128];
    int tid = threadIdx.x;
    if (tid < 128) { ssc[tid] = g_escale[tid]; ssh[tid] = g_eshift[tid]; }
    __syncthreads();
    int lane = tid & 31;
    int sub  = lane >> 4;       // edge within pair
    int l16  = lane & 15;       // 4-feature group
    int f = l16 * 4;
    float sg0 = ssc[f], sg1 = ssc[f+1], sg2 = ssc[f+2], sg3 = ssc[f+3];
    float hg0 = ssh[f], hg1 = ssh[f+1], hg2 = ssh[f+2], hg3 = ssh[f+3];
    float sc0 = ssc[64+f], sc1 = ssc[65+f], sc2 = ssc[66+f], sc3 = ssc[67+f];
    float hc0 = ssh[64+f], hc1 = ssh[65+f], hc2 = ssh[66+f], hc3 = ssh[67+f];

    int gw = (blockIdx.x * 256 + tid) >> 5;
    int nw = (gridDim.x * 256) >> 5;
    for (int e = gw * 2 + sub; e < NE; e += nw * 2) {
        const float4 yg = *(const float4*)(g_y + (size_t)e * HD + f);
        const float4 yc = *(const float4*)(g_y + (size_t)e * HD + 64 + f);
        float4 m;
        m.x = sigf(yg.x * sg0 + hg0) * spf(yc.x * sc0 + hc0);
        m.y = sigf(yg.y * sg1 + hg1) * spf(yc.y * sc1 + hc1);
        m.z = sigf(yg.z * sg2 + hg2) * spf(yc.z * sc2 + hc2);
        m.w = sigf(yg.w * sg3 + hg3) * spf(yc.w * sc3 + hc3);
        int n = idx1[e];
        red4(g_nodeacc + (size_t)n * NF + f, m);
    }
}

// ---------------- node BN stats / finalize / apply ----------------
__global__ void k_node_stats() {
    int tid = threadIdx.x;            // 256
    int f = tid & 63, nl = tid >> 6;  // 4 node lanes
    float s = 0.f, q = 0.f;
    for (int n = blockIdx.x * 4 + nl; n < NN; n += gridDim.x * 4) {
        float v = g_nodeacc[(size_t)n * NF + f] * g_inv1[n];
        s += v; q += v * v;
    }
    __shared__ float a1[256], a2[256];
    a1[tid] = s; a2[tid] = q;
    __syncthreads();
    if (tid < 64) {
        s = a1[tid] + a1[tid + 64] + a1[tid + 128] + a1[tid + 192];
        q = a2[tid] + a2[tid + 64] + a2[tid + 128] + a2[tid + 192];
        atomicAdd(&g_nstats[tid], s);
        atomicAdd(&g_nstats[64 + tid], q);
    }
}
__global__ void k_fin_node(const float* __restrict__ g2, const float* __restrict__ be2) {
    int j = threadIdx.x;             // 64
    float m  = g_nstats[j] * (1.f / (float)NN);
    float sq = g_nstats[64 + j] * (1.f / (float)NN);
    float rstd = rsqrtf(sq - m * m + BN_EPS);
    float sc = g2[j] * rstd;
    g_nscale[j] = sc;
    g_nshift[j] = be2[j] - m * sc;
}
__global__ void k_node_apply() {
    int i = blockIdx.x * blockDim.x + threadIdx.x;   // NN*16 float4s
    if (i >= NN * 16) return;
    int n = i >> 4, q = i & 15;
    float inv = g_inv1[n];
    float4 a = ((const float4*)g_nodeacc)[i];
    float4 x = ((const float4*)g_x)[i];
    float4 sc = ((const float4*)g_nscale)[q];
    float4 sh = ((const float4*)g_nshift)[q];
    float4 r;
    r.x = spf(x.x + a.x * inv * sc.x + sh.x);
    r.y = spf(x.y + a.y * inv * sc.y + sh.y);
    r.z = spf(x.z + a.z * inv * sc.z + sh.z);
    r.w = spf(x.w + a.w * inv * sc.w + sh.w);
    ((float4*)g_x)[i] = r;
}

// ---------------- crystal pooling + head ----------------
__global__ void k_crys_scatter(const int* __restrict__ idx3) {
    int i = blockIdx.x * blockDim.x + threadIdx.x;   // NN*16 float4s
    if (i >= NN * 16) return;
    int n = i >> 4, q = i & 15;
    float4 v = ((const float4*)g_x)[i];
    red4(g_crys + (size_t)idx3[n] * NF + q * 4, v);
}
__global__ void __launch_bounds__(128)
k_head(const float* __restrict__ Wc, const float* __restrict__ bc,
       const float* __restrict__ Wo, const float* __restrict__ bo,
       float* __restrict__ out) {
    __shared__ float cr[64];
    __shared__ float r0[128], r1[128];
    int c = blockIdx.x, tid = threadIdx.x;
    if (tid < 64) cr[tid] = g_crys[(size_t)c * NF + tid] * g_invc[c];
    __syncthreads();
    float acc = bc[tid];
    #pragma unroll
    for (int k = 0; k < 64; k++) acc += cr[k] * Wc[k * HD + tid];
    float h = spf(acc);
    r0[tid] = h * Wo[tid * 2 + 0];
    r1[tid] = h * Wo[tid * 2 + 1];
    __syncthreads();
    for (int s = 64; s > 0; s >>= 1) {
        if (tid < s) { r0[tid] += r0[tid + s]; r1[tid] += r1[tid + s]; }
        __syncthreads();
    }
    if (tid == 0) {
        out[c * 2 + 0] = r0[0] + bo[0];
        out[c * 2 + 1] = r1[0] + bo[1];
    }
}

// ---------------- launch ----------------
extern "C" void kernel_launch(void* const* d_in, const int* in_sizes, int n_in,
                              void* d_out, int out_size) {
    (void)in_sizes; (void)n_in; (void)out_size;
    const int*   node_fea = (const int*)  d_in[0];
    const float* edge_fea = (const float*)d_in[1];
    const int*   idx1     = (const int*)  d_in[2];
    const int*   idx2     = (const int*)  d_in[3];
    const int*   idx3     = (const int*)  d_in[4];
    const float* emb      = (const float*)d_in[5];
    const float* Wf       = (const float*)d_in[6];
    const float* bf       = (const float*)d_in[7];
    const float* g1       = (const float*)d_in[8];
    const float* be1      = (const float*)d_in[9];
    const float* g2       = (const float*)d_in[10];
    const float* be2      = (const float*)d_in[11];
    const float* Wc       = (const float*)d_in[12];
    const float* bc       = (const float*)d_in[13];
    const float* Wo       = (const float*)d_in[14];
    const float* bo       = (const float*)d_in[15];
    float* out = (float*)d_out;

    const size_t SMEM_A = (size_t)(KD * HD + HD + TE * ZLD + 256) * 4 + 2 * TE * 4;
    cudaFuncSetAttribute(k_passA, cudaFuncAttributeMaxDynamicSharedMemorySize, (int)SMEM_A);

    void *p_cnt1, *p_cntc, *p_stats, *p_nstats, *p_nodeacc, *p_crys;
    cudaGetSymbolAddress(&p_cnt1, g_cnt1);
    cudaGetSymbolAddress(&p_cntc, g_cntc);
    cudaGetSymbolAddress(&p_stats, g_stats);
    cudaGetSymbolAddress(&p_nstats, g_nstats);
    cudaGetSymbolAddress(&p_nodeacc, g_nodeacc);
    cudaGetSymbolAddress(&p_crys, g_crys);

    cudaMemsetAsync(p_cnt1, 0, (size_t)NN * 4);
    cudaMemsetAsync(p_cntc, 0, (size_t)NC * 4);
    k_count_edges<<<(NE + 255) / 256, 256>>>(idx1);
    k_count_crys<<<(NN + 255) / 256, 256>>>(idx3);
    k_inv<<<(NN + 255) / 256, 256>>>();
    k_embed<<<(NN * 16 + 255) / 256, 256>>>(node_fea, emb);

    for (int l = 0; l < NCONV; ++l) {
        cudaMemsetAsync(p_stats, 0, 256 * 4);
        cudaMemsetAsync(p_nstats, 0, 128 * 4);
        cudaMemsetAsync(p_nodeacc, 0, (size_t)NN * NF * 4);
        k_passA<<<148, 256, SMEM_A>>>(edge_fea, idx1, idx2,
                                      Wf + (size_t)l * KD * HD, bf + (size_t)l * HD);
        k_fin_edge<<<1, 128>>>(g1 + (size_t)l * HD, be1 + (size_t)l * HD);
        k_passB<<<1184, 256>>>(idx1);
        k_node_stats<<<592, 256>>>();
        k_fin_node<<<1, 64>>>(g2 + (size_t)l * NF, be2 + (size_t)l * NF);
        k_node_apply<<<(NN * 16 + 255) / 256, 256>>>();
    }

    cudaMemsetAsync(p_crys, 0, (size_t)NC * NF * 4);
    k_crys_scatter<<<(NN * 16 + 255) / 256, 256>>>(idx3);
    k_head<<<NC, 128>>>(Wc, bc, Wo, bo, out);
}

// round 4
// speedup vs baseline: 1.3441x; 1.3441x over previous
#include <cuda_runtime.h>
#include <cuda_bf16.h>
#include <cstdint>
#include <math.h>

#define NN 100000
#define NE 1600000
#define NC 2000
#define NF 64
#define EFD 41
#define KD 169
#define HD 128
#define NCONV 3
#define BN_EPS 1e-5f
#define NT 12500        // NE/128
#define GRID_A 148
#define KS 184          // padded K stride (bf16 elems), 368B rows
#define KSW 92          // in 32-bit words

// smem byte offsets for passA
#define SW_H 0
#define SW_L 47104
#define SA_H 94208
#define SA_L 141312
#define S_I1 188416
#define S_I2 188928
#define S_B  189440
#define SMEM_A 189952

// ---------------- scratch ----------------
static __device__ float g_x[(size_t)NN * NF];
static __device__ float g_y[(size_t)NE * HD];
static __device__ float g_nodeacc[(size_t)NN * NF];
static __device__ float g_crys[(size_t)NC * NF];
static __device__ float g_stats[256];      // sum[128] | sumsq[128]
static __device__ float g_nstats[128];
static __device__ float g_escale[128];
static __device__ float g_eshift[128];
static __device__ float g_nscale[64];
static __device__ float g_nshift[64];
static __device__ int   g_cnt1[NN];
static __device__ float g_inv1[NN];
static __device__ int   g_cntc[NC];
static __device__ float g_invc[NC];

// ---------------- helpers ----------------
__device__ __forceinline__ float spf(float x) { return (x > 20.f) ? x : log1pf(expf(x)); }
__device__ __forceinline__ float sigf(float x) { return 1.f / (1.f + expf(-x)); }
__device__ __forceinline__ void red4(float* p, float4 v) {
    asm volatile("red.global.add.v4.f32 [%0], {%1,%2,%3,%4};"
                 :: "l"(p), "f"(v.x), "f"(v.y), "f"(v.z), "f"(v.w) : "memory");
}
__device__ __forceinline__ uint32_t smem_u32(const void* p) {
    uint32_t a;
    asm("{ .reg .u64 t; cvta.to.shared.u64 t, %1; cvt.u32.u64 %0, t; }" : "=r"(a) : "l"(p));
    return a;
}
// pack two floats -> bf16x2 hi word + bf16x2 residual word
__device__ __forceinline__ void pack_hl(float v0, float v1, uint32_t& h, uint32_t& l) {
    __nv_bfloat162 h2 = __floats2bfloat162_rn(v0, v1);
    float f0 = __bfloat162float(h2.x), f1 = __bfloat162float(h2.y);
    __nv_bfloat162 l2 = __floats2bfloat162_rn(v0 - f0, v1 - f1);
    h = *(uint32_t*)&h2; l = *(uint32_t*)&l2;
}
__device__ __forceinline__ void ldm4(uint32_t* r, uint32_t a) {
    asm volatile("ldmatrix.sync.aligned.m8n8.x4.shared.b16 {%0,%1,%2,%3}, [%4];"
        : "=r"(r[0]), "=r"(r[1]), "=r"(r[2]), "=r"(r[3]) : "r"(a));
}
__device__ __forceinline__ void mma16816(float* d, const uint32_t* a, const uint32_t* b) {
    asm volatile("mma.sync.aligned.m16n8k16.row.col.f32.bf16.bf16.f32 "
        "{%0,%1,%2,%3}, {%4,%5,%6,%7}, {%8,%9}, {%0,%1,%2,%3};"
        : "+f"(d[0]), "+f"(d[1]), "+f"(d[2]), "+f"(d[3])
        : "r"(a[0]), "r"(a[1]), "r"(a[2]), "r"(a[3]), "r"(b[0]), "r"(b[1]));
}

// ---------------- setup kernels ----------------
__global__ void k_count_edges(const int* __restrict__ idx1) {
    int i = blockIdx.x * blockDim.x + threadIdx.x;
    if (i < NE) atomicAdd(&g_cnt1[idx1[i]], 1);
}
__global__ void k_count_crys(const int* __restrict__ idx3) {
    int i = blockIdx.x * blockDim.x + threadIdx.x;
    if (i < NN) atomicAdd(&g_cntc[idx3[i]], 1);
}
__global__ void k_inv() {
    int i = blockIdx.x * blockDim.x + threadIdx.x;
    if (i < NN) g_inv1[i] = 1.f / (float)max(g_cnt1[i], 1);
    if (i < NC) g_invc[i] = 1.f / (float)max(g_cntc[i], 1);
}
__global__ void k_embed(const int* __restrict__ node_fea, const float* __restrict__ emb) {
    int i = blockIdx.x * blockDim.x + threadIdx.x;
    if (i >= NN * 16) return;
    int n = i >> 4, q = i & 15;
    ((float4*)g_x)[i] = ((const float4*)emb)[node_fea[n] * 16 + q];
}

// ---------------- pass A: mma.sync bf16 3-term GEMM -> g_y + BN stats ------
__global__ void __launch_bounds__(256, 1)
k_passA(const float* __restrict__ ef, const int* __restrict__ idx1,
        const int* __restrict__ idx2, const float* __restrict__ W,
        const float* __restrict__ b) {
    extern __shared__ char sm[];
    const uint32_t sb = smem_u32(sm);
    uint32_t* sAHw = (uint32_t*)(sm + SA_H);
    uint32_t* sALw = (uint32_t*)(sm + SA_L);
    int*      sI1  = (int*)(sm + S_I1);
    int*      sI2  = (int*)(sm + S_I2);
    float*    sB   = (float*)(sm + S_B);

    const int tid = threadIdx.x;
    const int wid = tid >> 5;
    const int l   = tid & 31;
    const int mbase = (wid & 3) * 32;
    const int nbase = (wid >> 2) * 64;

    // W -> [n][k] bf16 hi/lo (K-contiguous, padded to KS)
    for (int i = tid; i < KS * HD; i += 256) {
        int k = i >> 7, n = i & 127;
        float w = (k < KD) ? W[k * HD + n] : 0.f;
        __nv_bfloat16 h = __float2bfloat16(w);
        __nv_bfloat16 lo = __float2bfloat16(w - __bfloat162float(h));
        *(uint16_t*)(sm + SW_H + ((size_t)n * KS + k) * 2) = *(uint16_t*)&h;
        *(uint16_t*)(sm + SW_L + ((size_t)n * KS + k) * 2) = *(uint16_t*)&lo;
    }
    if (tid < 128) sB[tid] = b[tid];

    // ldmatrix base addresses (fixed across tiles; k-step adds 32B)
    uint32_t aH0 = sb + SA_H + (uint32_t)(((mbase + (l & 15)) * KS + (l >> 4) * 8) * 2);
    uint32_t aH1 = aH0 + 16 * KS * 2;
    uint32_t aL0 = aH0 + (SA_L - SA_H);
    uint32_t aL1 = aH1 + (SA_L - SA_H);
    uint32_t bH[4], bL[4];
    #pragma unroll
    for (int np = 0; np < 4; np++) {
        int n = nbase + np * 16 + ((l >> 4) * 8) + (l & 7);
        uint32_t off = (uint32_t)((n * KS + ((l >> 3) & 1) * 8) * 2);
        bH[np] = sb + SW_H + off;
        bL[np] = sb + SW_L + off;
    }

    float accS[16], accQ[16];
    #pragma unroll
    for (int i = 0; i < 16; i++) { accS[i] = 0.f; accQ[i] = 0.f; }

    for (int t = blockIdx.x; t < NT; t += GRID_A) {
        const int e0 = t * 128;
        __syncthreads();     // prior tile's smem reads complete (also W ready, iter 0)
        if (tid < 128) { sI1[tid] = idx1[e0 + tid]; sI2[tid] = idx2[e0 + tid]; }
        __syncthreads();
        // gather node features -> bf16 hi/lo rows [m][k], k 0..127
        #pragma unroll
        for (int it = 0; it < 16; ++it) {
            int i = tid + it * 256;           // e fixed per warp: conflict-free
            int e = i >> 5, q = i & 31;
            const float4 v = (q < 16)
                ? ((const float4*)(g_x + (size_t)sI1[e] * NF))[q]
                : ((const float4*)(g_x + (size_t)sI2[e] * NF))[q - 16];
            uint32_t h0, l0, h1, l1;
            pack_hl(v.x, v.y, h0, l0);
            pack_hl(v.z, v.w, h1, l1);
            int wo = e * KSW + q * 2;
            *(uint2*)(sAHw + wo) = make_uint2(h0, h1);
            *(uint2*)(sALw + wo) = make_uint2(l0, l1);
        }
        // edge features: words 64..91 per row (cols 128..183, zero pad >=169)
        for (int i = tid; i < 128 * 28; i += 256) {
            int e = i / 28, m = i - e * 28;
            int k0 = 128 + 2 * m;
            const float* efr = ef + (size_t)(e0 + e) * EFD;
            float v0 = (k0 < KD) ? efr[k0 - 128] : 0.f;
            float v1 = (k0 + 1 < KD) ? efr[k0 - 127] : 0.f;
            uint32_t h, lo;
            pack_hl(v0, v1, h, lo);
            sAHw[e * KSW + 64 + m] = h;
            sALw[e * KSW + 64 + m] = lo;
        }
        __syncthreads();

        // ------- MMA: acc[mt][nt][4] over 11 k-steps, 3 split terms -------
        float acc[2][8][4];
        #pragma unroll
        for (int mt = 0; mt < 2; mt++)
            #pragma unroll
            for (int nt = 0; nt < 8; nt++)
                #pragma unroll
                for (int r = 0; r < 4; r++) acc[mt][nt][r] = 0.f;

        for (int ks = 0; ks < 11; ks++) {
            const uint32_t ko = (uint32_t)ks * 32u;
            uint32_t ah[2][4], al[2][4], bh[4][4], bl[4][4];
            ldm4(ah[0], aH0 + ko); ldm4(ah[1], aH1 + ko);
            ldm4(al[0], aL0 + ko); ldm4(al[1], aL1 + ko);
            #pragma unroll
            for (int np = 0; np < 4; np++) { ldm4(bh[np], bH[np] + ko); ldm4(bl[np], bL[np] + ko); }
            #pragma unroll
            for (int mt = 0; mt < 2; mt++)
                #pragma unroll
                for (int np = 0; np < 4; np++)
                    #pragma unroll
                    for (int hf = 0; hf < 2; hf++) {
                        int nt = np * 2 + hf;
                        mma16816(acc[mt][nt], ah[mt], &bh[np][hf * 2]);
                        mma16816(acc[mt][nt], al[mt], &bh[np][hf * 2]);
                        mma16816(acc[mt][nt], ah[mt], &bl[np][hf * 2]);
                    }
        }

        // ------- epilogue: bias, BN stats, write y -------
        #pragma unroll
        for (int mt = 0; mt < 2; mt++) {
            int r0 = e0 + mbase + mt * 16 + (l >> 2);
            float* y0 = g_y + (size_t)r0 * HD;
            float* y1 = y0 + 8 * HD;
            #pragma unroll
            for (int nt = 0; nt < 8; nt++) {
                int c = nbase + nt * 8 + 2 * (l & 3);
                float b0 = sB[c], b1 = sB[c + 1];
                float v0 = acc[mt][nt][0] + b0, v1 = acc[mt][nt][1] + b1;
                float v2 = acc[mt][nt][2] + b0, v3 = acc[mt][nt][3] + b1;
                accS[nt * 2]     += v0 + v2;
                accS[nt * 2 + 1] += v1 + v3;
                accQ[nt * 2]     += v0 * v0 + v2 * v2;
                accQ[nt * 2 + 1] += v1 * v1 + v3 * v3;
                *(float2*)(y0 + c) = make_float2(v0, v1);
                *(float2*)(y1 + c) = make_float2(v2, v3);
            }
        }
    }
    // flush BN stats: reduce over the 8 lanes sharing (l&3)
    #pragma unroll
    for (int j = 0; j < 16; j++) {
        float s = accS[j], q = accQ[j];
        #pragma unroll
        for (int o = 4; o < 32; o <<= 1) {
            s += __shfl_xor_sync(0xFFFFFFFFu, s, o);
            q += __shfl_xor_sync(0xFFFFFFFFu, q, o);
        }
        if (l < 4) {
            int col = nbase + (j >> 1) * 8 + 2 * l + (j & 1);
            atomicAdd(&g_stats[col], s);
            atomicAdd(&g_stats[128 + col], q);
        }
    }
}

__global__ void k_fin_edge(const float* __restrict__ g1, const float* __restrict__ be1) {
    int j = threadIdx.x;
    float m  = g_stats[j] * (1.f / (float)NE);
    float sq = g_stats[128 + j] * (1.f / (float)NE);
    float sc = g1[j] * rsqrtf(sq - m * m + BN_EPS);
    g_escale[j] = sc;
    g_eshift[j] = be1[j] - m * sc;
}

// ---------------- pass B ----------------
__global__ void __launch_bounds__(256)
k_passB(const int* __restrict__ idx1) {
    __shared__ float ssc[128], ssh[128];
    int tid = threadIdx.x;
    if (tid < 128) { ssc[tid] = g_escale[tid]; ssh[tid] = g_eshift[tid]; }
    __syncthreads();
    int lane = tid & 31;
    int sub = lane >> 4, l16 = lane & 15;
    int f = l16 * 4;
    float sg0 = ssc[f], sg1 = ssc[f+1], sg2 = ssc[f+2], sg3 = ssc[f+3];
    float hg0 = ssh[f], hg1 = ssh[f+1], hg2 = ssh[f+2], hg3 = ssh[f+3];
    float sc0 = ssc[64+f], sc1 = ssc[65+f], sc2 = ssc[66+f], sc3 = ssc[67+f];
    float hc0 = ssh[64+f], hc1 = ssh[65+f], hc2 = ssh[66+f], hc3 = ssh[67+f];
    int gw = (blockIdx.x * 256 + tid) >> 5;
    int nw = (gridDim.x * 256) >> 5;
    for (int e = gw * 2 + sub; e < NE; e += nw * 2) {
        const float4 yg = *(const float4*)(g_y + (size_t)e * HD + f);
        const float4 yc = *(const float4*)(g_y + (size_t)e * HD + 64 + f);
        float4 m;
        m.x = sigf(yg.x * sg0 + hg0) * spf(yc.x * sc0 + hc0);
        m.y = sigf(yg.y * sg1 + hg1) * spf(yc.y * sc1 + hc1);
        m.z = sigf(yg.z * sg2 + hg2) * spf(yc.z * sc2 + hc2);
        m.w = sigf(yg.w * sg3 + hg3) * spf(yc.w * sc3 + hc3);
        red4(g_nodeacc + (size_t)idx1[e] * NF + f, m);
    }
}

// ---------------- node BN ----------------
__global__ void k_node_stats() {
    int tid = threadIdx.x;
    int f = tid & 63, nl = tid >> 6;
    float s = 0.f, q = 0.f;
    for (int n = blockIdx.x * 4 + nl; n < NN; n += gridDim.x * 4) {
        float v = g_nodeacc[(size_t)n * NF + f] * g_inv1[n];
        s += v; q += v * v;
    }
    __shared__ float a1[256], a2[256];
    a1[tid] = s; a2[tid] = q;
    __syncthreads();
    if (tid < 64) {
        s = a1[tid] + a1[tid + 64] + a1[tid + 128] + a1[tid + 192];
        q = a2[tid] + a2[tid + 64] + a2[tid + 128] + a2[tid + 192];
        atomicAdd(&g_nstats[tid], s);
        atomicAdd(&g_nstats[64 + tid], q);
    }
}
__global__ void k_fin_node(const float* __restrict__ g2, const float* __restrict__ be2) {
    int j = threadIdx.x;
    float m  = g_nstats[j] * (1.f / (float)NN);
    float sq = g_nstats[64 + j] * (1.f / (float)NN);
    float sc = g2[j] * rsqrtf(sq - m * m + BN_EPS);
    g_nscale[j] = sc;
    g_nshift[j] = be2[j] - m * sc;
}
__global__ void k_node_apply() {
    int i = blockIdx.x * blockDim.x + threadIdx.x;
    if (i >= NN * 16) return;
    int n = i >> 4, q = i & 15;
    float inv = g_inv1[n];
    float4 a = ((const float4*)g_nodeacc)[i];
    float4 x = ((const float4*)g_x)[i];
    float4 sc = ((const float4*)g_nscale)[q];
    float4 sh = ((const float4*)g_nshift)[q];
    float4 r;
    r.x = spf(x.x + a.x * inv * sc.x + sh.x);
    r.y = spf(x.y + a.y * inv * sc.y + sh.y);
    r.z = spf(x.z + a.z * inv * sc.z + sh.z);
    r.w = spf(x.w + a.w * inv * sc.w + sh.w);
    ((float4*)g_x)[i] = r;
}

// ---------------- crystal pooling + head ----------------
__global__ void k_crys_scatter(const int* __restrict__ idx3) {
    int i = blockIdx.x * blockDim.x + threadIdx.x;
    if (i >= NN * 16) return;
    int n = i >> 4, q = i & 15;
    red4(g_crys + (size_t)idx3[n] * NF + q * 4, ((const float4*)g_x)[i]);
}
__global__ void __launch_bounds__(128)
k_head(const float* __restrict__ Wc, const float* __restrict__ bc,
       const float* __restrict__ Wo, const float* __restrict__ bo,
       float* __restrict__ out) {
    __shared__ float cr[64];
    __shared__ float r0[128], r1[128];
    int c = blockIdx.x, tid = threadIdx.x;
    if (tid < 64) cr[tid] = g_crys[(size_t)c * NF + tid] * g_invc[c];
    __syncthreads();
    float acc = bc[tid];
    #pragma unroll
    for (int k = 0; k < 64; k++) acc += cr[k] * Wc[k * HD + tid];
    float h = spf(acc);
    r0[tid] = h * Wo[tid * 2 + 0];
    r1[tid] = h * Wo[tid * 2 + 1];
    __syncthreads();
    for (int s = 64; s > 0; s >>= 1) {
        if (tid < s) { r0[tid] += r0[tid + s]; r1[tid] += r1[tid + s]; }
        __syncthreads();
    }
    if (tid == 0) {
        out[c * 2 + 0] = r0[0] + bo[0];
        out[c * 2 + 1] = r1[0] + bo[1];
    }
}

// ---------------- launch ----------------
extern "C" void kernel_launch(void* const* d_in, const int* in_sizes, int n_in,
                              void* d_out, int out_size) {
    (void)in_sizes; (void)n_in; (void)out_size;
    const int*   node_fea = (const int*)  d_in[0];
    const float* edge_fea = (const float*)d_in[1];
    const int*   idx1     = (const int*)  d_in[2];
    const int*   idx2     = (const int*)  d_in[3];
    const int*   idx3     = (const int*)  d_in[4];
    const float* emb      = (const float*)d_in[5];
    const float* Wf       = (const float*)d_in[6];
    const float* bf       = (const float*)d_in[7];
    const float* g1       = (const float*)d_in[8];
    const float* be1      = (const float*)d_in[9];
    const float* g2       = (const float*)d_in[10];
    const float* be2      = (const float*)d_in[11];
    const float* Wc       = (const float*)d_in[12];
    const float* bc       = (const float*)d_in[13];
    const float* Wo       = (const float*)d_in[14];
    const float* bo       = (const float*)d_in[15];
    float* out = (float*)d_out;

    cudaFuncSetAttribute(k_passA, cudaFuncAttributeMaxDynamicSharedMemorySize, SMEM_A);

    void *p_cnt1, *p_cntc, *p_stats, *p_nstats, *p_nodeacc, *p_crys;
    cudaGetSymbolAddress(&p_cnt1, g_cnt1);
    cudaGetSymbolAddress(&p_cntc, g_cntc);
    cudaGetSymbolAddress(&p_stats, g_stats);
    cudaGetSymbolAddress(&p_nstats, g_nstats);
    cudaGetSymbolAddress(&p_nodeacc, g_nodeacc);
    cudaGetSymbolAddress(&p_crys, g_crys);

    cudaMemsetAsync(p_cnt1, 0, (size_t)NN * 4);
    cudaMemsetAsync(p_cntc, 0, (size_t)NC * 4);
    k_count_edges<<<(NE + 255) / 256, 256>>>(idx1);
    k_count_crys<<<(NN + 255) / 256, 256>>>(idx3);
    k_inv<<<(NN + 255) / 256, 256>>>();
    k_embed<<<(NN * 16 + 255) / 256, 256>>>(node_fea, emb);

    for (int l = 0; l < NCONV; ++l) {
        cudaMemsetAsync(p_stats, 0, 256 * 4);
        cudaMemsetAsync(p_nstats, 0, 128 * 4);
        cudaMemsetAsync(p_nodeacc, 0, (size_t)NN * NF * 4);
        k_passA<<<GRID_A, 256, SMEM_A>>>(edge_fea, idx1, idx2,
                                         Wf + (size_t)l * KD * HD, bf + (size_t)l * HD);
        k_fin_edge<<<1, 128>>>(g1 + (size_t)l * HD, be1 + (size_t)l * HD);
        k_passB<<<1184, 256>>>(idx1);
        k_node_stats<<<592, 256>>>();
        k_fin_node<<<1, 64>>>(g2 + (size_t)l * NF, be2 + (size_t)l * NF);
        k_node_apply<<<(NN * 16 + 255) / 256, 256>>>();
    }

    cudaMemsetAsync(p_crys, 0, (size_t)NC * NF * 4);
    k_crys_scatter<<<(NN * 16 + 255) / 256, 256>>>(idx3);
    k_head<<<NC, 128>>>(Wc, bc, Wo, bo, out);
}

// round 6
// speedup vs baseline: 1.7849x; 1.3280x over previous
#include <cuda_runtime.h>
#include <cuda_bf16.h>
#include <cstdint>
#include <math.h>

#define NN 100000
#define NE 1600000
#define NC 2000
#define NF 64
#define EFD 41
#define KD 169
#define HD 128
#define NCONV 3
#define BN_EPS 1e-5f
#define NT 12500        // NE/128
#define GRID_A 148
#define KS2 56          // padded ef-K stride (bf16 elems), 112B rows

// smem byte offsets for passA (ef-only A tile, K=48)
#define SW_H 0
#define SW_L 14336
#define SA_H 28672
#define SA_L 43008
#define S_I1 57344
#define S_I2 57856
#define S_B  58368
#define SMEM_A 58880

// ---------------- scratch ----------------
static __device__ float g_x[(size_t)NN * NF];
static __device__ float g_P[(size_t)NN * 256];   // x@W1 | x@W2 per node
static __device__ float g_y[(size_t)NE * HD];
static __device__ float g_nodeacc[(size_t)NN * NF];
static __device__ float g_crys[(size_t)NC * NF];
static __device__ float g_stats[256];      // sum[128] | sumsq[128]
static __device__ float g_nstats[128];
static __device__ float g_escale[128];
static __device__ float g_eshift[128];
static __device__ float g_nscale[64];
static __device__ float g_nshift[64];
static __device__ int   g_cnt1[NN];
static __device__ float g_inv1[NN];
static __device__ int   g_cntc[NC];
static __device__ float g_invc[NC];

// ---------------- helpers ----------------
__device__ __forceinline__ float spf(float x) { return (x > 20.f) ? x : log1pf(expf(x)); }
__device__ __forceinline__ float sigf(float x) { return 1.f / (1.f + expf(-x)); }
__device__ __forceinline__ void red4(float* p, float4 v) {
    asm volatile("red.global.add.v4.f32 [%0], {%1,%2,%3,%4};"
                 :: "l"(p), "f"(v.x), "f"(v.y), "f"(v.z), "f"(v.w) : "memory");
}
__device__ __forceinline__ uint32_t smem_u32(const void* p) {
    uint32_t a;
    asm("{ .reg .u64 t; cvta.to.shared.u64 t, %1; cvt.u32.u64 %0, t; }" : "=r"(a) : "l"(p));
    return a;
}
__device__ __forceinline__ void ldm4(uint32_t* r, uint32_t a) {
    asm volatile("ldmatrix.sync.aligned.m8n8.x4.shared.b16 {%0,%1,%2,%3}, [%4];"
        : "=r"(r[0]), "=r"(r[1]), "=r"(r[2]), "=r"(r[3]) : "r"(a));
}
__device__ __forceinline__ void mma16816(float* d, const uint32_t* a, const uint32_t* b) {
    asm volatile("mma.sync.aligned.m16n8k16.row.col.f32.bf16.bf16.f32 "
        "{%0,%1,%2,%3}, {%4,%5,%6,%7}, {%8,%9}, {%0,%1,%2,%3};"
        : "+f"(d[0]), "+f"(d[1]), "+f"(d[2]), "+f"(d[3])
        : "r"(a[0]), "r"(a[1]), "r"(a[2]), "r"(a[3]), "r"(b[0]), "r"(b[1]));
}

// ---------------- setup kernels ----------------
__global__ void k_count_edges(const int* __restrict__ idx1) {
    int i = blockIdx.x * blockDim.x + threadIdx.x;
    if (i < NE) atomicAdd(&g_cnt1[idx1[i]], 1);
}
__global__ void k_count_crys(const int* __restrict__ idx3) {
    int i = blockIdx.x * blockDim.x + threadIdx.x;
    if (i < NN) atomicAdd(&g_cntc[idx3[i]], 1);
}
__global__ void k_inv() {
    int i = blockIdx.x * blockDim.x + threadIdx.x;
    if (i < NN) g_inv1[i] = 1.f / (float)max(g_cnt1[i], 1);
    if (i < NC) g_invc[i] = 1.f / (float)max(g_cntc[i], 1);
}
__global__ void k_embed(const int* __restrict__ node_fea, const float* __restrict__ emb) {
    int i = blockIdx.x * blockDim.x + threadIdx.x;
    if (i >= NN * 16) return;
    int n = i >> 4, q = i & 15;
    ((float4*)g_x)[i] = ((const float4*)emb)[node_fea[n] * 16 + q];
}

// ---------------- node pre-GEMM: P = x @ [W1 | W2]  (fp32) ----------------
__global__ void __launch_bounds__(256, 1)
k_nodeP(const float* __restrict__ W) {
    extern __shared__ float sw[];
    float* sW = sw;              // [64][256]
    float* sX = sw + 64 * 256;   // [64][65]
    const int tid = threadIdx.x;
    // Wcat[k][c]: c<128 -> W[k][c]; else W[64+k][c-128]
    for (int i = tid; i < 64 * 256; i += 256) {
        int k = i >> 8, c = i & 255;
        sW[i] = (c < 128) ? W[k * HD + c] : W[(64 + k) * HD + (c - 128)];
    }
    const int nb = blockIdx.x * 64;
    for (int i = tid; i < 64 * 64; i += 256) {
        int r = i >> 6, k = i & 63;
        sX[r * 65 + k] = (nb + r < NN) ? g_x[(size_t)(nb + r) * NF + k] : 0.f;
    }
    __syncthreads();
    const int tx = tid & 31;     // col group of 8
    const int ty = tid >> 5;     // node group of 8
    const int c0 = tx * 8;
    float acc[8][8];
    #pragma unroll
    for (int i = 0; i < 8; i++)
        #pragma unroll
        for (int j = 0; j < 8; j++) acc[i][j] = 0.f;
    #pragma unroll 4
    for (int k = 0; k < 64; k++) {
        float wv[8];
        #pragma unroll
        for (int j = 0; j < 8; j++) wv[j] = sW[k * 256 + c0 + j];
        #pragma unroll
        for (int i = 0; i < 8; i++) {
            float xv = sX[(ty * 8 + i) * 65 + k];
            #pragma unroll
            for (int j = 0; j < 8; j++) acc[i][j] += xv * wv[j];
        }
    }
    #pragma unroll
    for (int i = 0; i < 8; i++) {
        int n = nb + ty * 8 + i;
        if (n < NN) {
            float* dst = g_P + (size_t)n * 256 + c0;
            *(float4*)dst       = make_float4(acc[i][0], acc[i][1], acc[i][2], acc[i][3]);
            *(float4*)(dst + 4) = make_float4(acc[i][4], acc[i][5], acc[i][6], acc[i][7]);
        }
    }
}

// ------- pass A: y = ef@W3 (mma, 3-term bf16) + P[idx1]+P[idx2]+b; stats ----
__global__ void __launch_bounds__(256, 1)
k_passA(const float* __restrict__ ef, const int* __restrict__ idx1,
        const int* __restrict__ idx2, const float* __restrict__ W,
        const float* __restrict__ b) {
    extern __shared__ char sm[];
    const uint32_t sb = smem_u32(sm);
    int*   sI1 = (int*)(sm + S_I1);
    int*   sI2 = (int*)(sm + S_I2);
    float* sB  = (float*)(sm + S_B);

    const int tid = threadIdx.x;
    const int wid = tid >> 5;
    const int l   = tid & 31;
    const int mbase = (wid & 3) * 32;
    const int nbase = (wid >> 2) * 64;

    // W3 (rows 128..168 of W) -> [n][k] bf16 hi/lo, K padded to 48/KS2
    for (int i = tid; i < HD * KS2; i += 256) {
        int n = i / KS2, k = i - n * KS2;
        float w = (k < EFD) ? W[(128 + k) * HD + n] : 0.f;
        __nv_bfloat16 h = __float2bfloat16(w);
        __nv_bfloat16 lo = __float2bfloat16(w - __bfloat162float(h));
        *(uint16_t*)(sm + SW_H + (size_t)i * 2) = *(uint16_t*)&h;
        *(uint16_t*)(sm + SW_L + (size_t)i * 2) = *(uint16_t*)&lo;
    }
    // zero A pad region once (k 41..55 never rewritten)
    for (int i = tid; i < 128 * (KS2 - EFD); i += 256) {
        int e = i / (KS2 - EFD), r = EFD + i % (KS2 - EFD);
        *(uint16_t*)(sm + SA_H + (size_t)(e * KS2 + r) * 2) = 0;
        *(uint16_t*)(sm + SA_L + (size_t)(e * KS2 + r) * 2) = 0;
    }
    if (tid < 128) sB[tid] = b[tid];

    // ldmatrix base addresses
    uint32_t aH0 = sb + SA_H + (uint32_t)(((mbase + (l & 15)) * KS2 + (l >> 4) * 8) * 2);
    uint32_t aH1 = aH0 + 16 * KS2 * 2;
    uint32_t aL0 = aH0 + (SA_L - SA_H);
    uint32_t aL1 = aH1 + (SA_L - SA_H);
    uint32_t bH[4], bL[4];
    #pragma unroll
    for (int np = 0; np < 4; np++) {
        int n = nbase + np * 16 + ((l >> 4) * 8) + (l & 7);
        uint32_t off = (uint32_t)((n * KS2 + ((l >> 3) & 1) * 8) * 2);
        bH[np] = sb + SW_H + off;
        bL[np] = sb + SW_L + off;
    }

    float accS[16], accQ[16];
    #pragma unroll
    for (int i = 0; i < 16; i++) { accS[i] = 0.f; accQ[i] = 0.f; }

    for (int t = blockIdx.x; t < NT; t += GRID_A) {
        const int e0 = t * 128;
        __syncthreads();   // prior tile's smem/sI reads complete (W/pad ready, iter 0)
        if (tid < 128) { sI1[tid] = idx1[e0 + tid]; sI2[tid] = idx2[e0 + tid]; }
        // ef gather: coalesced, convert to bf16 hi/lo
        for (int i = tid; i < 128 * EFD; i += 256) {
            float v = ef[(size_t)e0 * EFD + i];
            int e = i / EFD, r = i - e * EFD;
            __nv_bfloat16 h = __float2bfloat16(v);
            __nv_bfloat16 lo = __float2bfloat16(v - __bfloat162float(h));
            *(uint16_t*)(sm + SA_H + (size_t)(e * KS2 + r) * 2) = *(uint16_t*)&h;
            *(uint16_t*)(sm + SA_L + (size_t)(e * KS2 + r) * 2) = *(uint16_t*)&lo;
        }
        __syncthreads();

        float acc[2][8][4];
        #pragma unroll
        for (int mt = 0; mt < 2; mt++)
            #pragma unroll
            for (int nt = 0; nt < 8; nt++)
                #pragma unroll
                for (int r = 0; r < 4; r++) acc[mt][nt][r] = 0.f;

        #pragma unroll
        for (int ks = 0; ks < 3; ks++) {
            const uint32_t ko = (uint32_t)ks * 32u;
            uint32_t ah[2][4], al[2][4], bh[4][4], bl[4][4];
            ldm4(ah[0], aH0 + ko); ldm4(ah[1], aH1 + ko);
            ldm4(al[0], aL0 + ko); ldm4(al[1], aL1 + ko);
            #pragma unroll
            for (int np = 0; np < 4; np++) { ldm4(bh[np], bH[np] + ko); ldm4(bl[np], bL[np] + ko); }
            #pragma unroll
            for (int mt = 0; mt < 2; mt++)
                #pragma unroll
                for (int np = 0; np < 4; np++)
                    #pragma unroll
                    for (int hf = 0; hf < 2; hf++) {
                        int nt = np * 2 + hf;
                        mma16816(acc[mt][nt], ah[mt], &bh[np][hf * 2]);
                        mma16816(acc[mt][nt], al[mt], &bh[np][hf * 2]);
                        mma16816(acc[mt][nt], ah[mt], &bl[np][hf * 2]);
                    }
        }

        // epilogue: + P[idx1] + P[idx2] + bias; BN stats; write y
        #pragma unroll
        for (int mt = 0; mt < 2; mt++) {
            int ea = mbase + mt * 16 + (l >> 2);
            int eb = ea + 8;
            const float* p1a = g_P + (size_t)sI1[ea] * 256;
            const float* p2a = g_P + (size_t)sI2[ea] * 256 + 128;
            const float* p1b = g_P + (size_t)sI1[eb] * 256;
            const float* p2b = g_P + (size_t)sI2[eb] * 256 + 128;
            float* y0 = g_y + (size_t)(e0 + ea) * HD;
            float* y1 = g_y + (size_t)(e0 + eb) * HD;
            #pragma unroll
            for (int nt = 0; nt < 8; nt++) {
                int c = nbase + nt * 8 + 2 * (l & 3);
                float2 q1a = *(const float2*)(p1a + c);
                float2 q2a = *(const float2*)(p2a + c);
                float2 q1b = *(const float2*)(p1b + c);
                float2 q2b = *(const float2*)(p2b + c);
                float b0 = sB[c], b1 = sB[c + 1];
                float v0 = acc[mt][nt][0] + b0 + q1a.x + q2a.x;
                float v1 = acc[mt][nt][1] + b1 + q1a.y + q2a.y;
                float v2 = acc[mt][nt][2] + b0 + q1b.x + q2b.x;
                float v3 = acc[mt][nt][3] + b1 + q1b.y + q2b.y;
                accS[nt * 2]     += v0 + v2;
                accS[nt * 2 + 1] += v1 + v3;
                accQ[nt * 2]     += v0 * v0 + v2 * v2;
                accQ[nt * 2 + 1] += v1 * v1 + v3 * v3;
                *(float2*)(y0 + c) = make_float2(v0, v1);
                *(float2*)(y1 + c) = make_float2(v2, v3);
            }
        }
    }
    // flush BN stats
    #pragma unroll
    for (int j = 0; j < 16; j++) {
        float s = accS[j], q = accQ[j];
        #pragma unroll
        for (int o = 4; o < 32; o <<= 1) {
            s += __shfl_xor_sync(0xFFFFFFFFu, s, o);
            q += __shfl_xor_sync(0xFFFFFFFFu, q, o);
        }
        if (l < 4) {
            int col = nbase + (j >> 1) * 8 + 2 * l + (j & 1);
            atomicAdd(&g_stats[col], s);
            atomicAdd(&g_stats[128 + col], q);
        }
    }
}

__global__ void k_fin_edge(const float* __restrict__ g1, const float* __restrict__ be1) {
    int j = threadIdx.x;
    float m  = g_stats[j] * (1.f / (float)NE);
    float sq = g_stats[128 + j] * (1.f / (float)NE);
    float sc = g1[j] * rsqrtf(sq - m * m + BN_EPS);
    g_escale[j] = sc;
    g_eshift[j] = be1[j] - m * sc;
}

// ---------------- pass B ----------------
__global__ void __launch_bounds__(256)
k_passB(const int* __restrict__ idx1) {
    __shared__ float ssc[128], ssh[128];
    int tid = threadIdx.x;
    if (tid < 128) { ssc[tid] = g_escale[tid]; ssh[tid] = g_eshift[tid]; }
    __syncthreads();
    int lane = tid & 31;
    int sub = lane >> 4, l16 = lane & 15;
    int f = l16 * 4;
    float sg0 = ssc[f], sg1 = ssc[f+1], sg2 = ssc[f+2], sg3 = ssc[f+3];
    float hg0 = ssh[f], hg1 = ssh[f+1], hg2 = ssh[f+2], hg3 = ssh[f+3];
    float sc0 = ssc[64+f], sc1 = ssc[65+f], sc2 = ssc[66+f], sc3 = ssc[67+f];
    float hc0 = ssh[64+f], hc1 = ssh[65+f], hc2 = ssh[66+f], hc3 = ssh[67+f];
    int gw = (blockIdx.x * 256 + tid) >> 5;
    int nw = (gridDim.x * 256) >> 5;
    for (int e = gw * 2 + sub; e < NE; e += nw * 2) {
        const float4 yg = *(const float4*)(g_y + (size_t)e * HD + f);
        const float4 yc = *(const float4*)(g_y + (size_t)e * HD + 64 + f);
        float4 m;
        m.x = sigf(yg.x * sg0 + hg0) * spf(yc.x * sc0 + hc0);
        m.y = sigf(yg.y * sg1 + hg1) * spf(yc.y * sc1 + hc1);
        m.z = sigf(yg.z * sg2 + hg2) * spf(yc.z * sc2 + hc2);
        m.w = sigf(yg.w * sg3 + hg3) * spf(yc.w * sc3 + hc3);
        red4(g_nodeacc + (size_t)idx1[e] * NF + f, m);
    }
}

// ---------------- node BN ----------------
__global__ void k_node_stats() {
    int tid = threadIdx.x;
    int f = tid & 63, nl = tid >> 6;
    float s = 0.f, q = 0.f;
    for (int n = blockIdx.x * 4 + nl; n < NN; n += gridDim.x * 4) {
        float v = g_nodeacc[(size_t)n * NF + f] * g_inv1[n];
        s += v; q += v * v;
    }
    __shared__ float a1[256], a2[256];
    a1[tid] = s; a2[tid] = q;
    __syncthreads();
    if (tid < 64) {
        s = a1[tid] + a1[tid + 64] + a1[tid + 128] + a1[tid + 192];
        q = a2[tid] + a2[tid + 64] + a2[tid + 128] + a2[tid + 192];
        atomicAdd(&g_nstats[tid], s);
        atomicAdd(&g_nstats[64 + tid], q);
    }
}
__global__ void k_fin_node(const float* __restrict__ g2, const float* __restrict__ be2) {
    int j = threadIdx.x;
    float m  = g_nstats[j] * (1.f / (float)NN);
    float sq = g_nstats[64 + j] * (1.f / (float)NN);
    float sc = g2[j] * rsqrtf(sq - m * m + BN_EPS);
    g_nscale[j] = sc;
    g_nshift[j] = be2[j] - m * sc;
}
__global__ void k_node_apply() {
    int i = blockIdx.x * blockDim.x + threadIdx.x;
    if (i >= NN * 16) return;
    int n = i >> 4, q = i & 15;
    float inv = g_inv1[n];
    float4 a = ((const float4*)g_nodeacc)[i];
    float4 x = ((const float4*)g_x)[i];
    float4 sc = ((const float4*)g_nscale)[q];
    float4 sh = ((const float4*)g_nshift)[q];
    float4 r;
    r.x = spf(x.x + a.x * inv * sc.x + sh.x);
    r.y = spf(x.y + a.y * inv * sc.y + sh.y);
    r.z = spf(x.z + a.z * inv * sc.z + sh.z);
    r.w = spf(x.w + a.w * inv * sc.w + sh.w);
    ((float4*)g_x)[i] = r;
}

// ---------------- crystal pooling + head ----------------
__global__ void k_crys_scatter(const int* __restrict__ idx3) {
    int i = blockIdx.x * blockDim.x + threadIdx.x;
    if (i >= NN * 16) return;
    int n = i >> 4, q = i & 15;
    red4(g_crys + (size_t)idx3[n] * NF + q * 4, ((const float4*)g_x)[i]);
}
__global__ void __launch_bounds__(128)
k_head(const float* __restrict__ Wc, const float* __restrict__ bc,
       const float* __restrict__ Wo, const float* __restrict__ bo,
       float* __restrict__ out) {
    __shared__ float cr[64];
    __shared__ float r0[128], r1[128];
    int c = blockIdx.x, tid = threadIdx.x;
    if (tid < 64) cr[tid] = g_crys[(size_t)c * NF + tid] * g_invc[c];
    __syncthreads();
    float acc = bc[tid];
    #pragma unroll
    for (int k = 0; k < 64; k++) acc += cr[k] * Wc[k * HD + tid];
    float h = spf(acc);
    r0[tid] = h * Wo[tid * 2 + 0];
    r1[tid] = h * Wo[tid * 2 + 1];
    __syncthreads();
    for (int s = 64; s > 0; s >>= 1) {
        if (tid < s) { r0[tid] += r0[tid + s]; r1[tid] += r1[tid + s]; }
        __syncthreads();
    }
    if (tid == 0) {
        out[c * 2 + 0] = r0[0] + bo[0];
        out[c * 2 + 1] = r1[0] + bo[1];
    }
}

// ---------------- launch ----------------
extern "C" void kernel_launch(void* const* d_in, const int* in_sizes, int n_in,
                              void* d_out, int out_size) {
    (void)in_sizes; (void)n_in; (void)out_size;
    const int*   node_fea = (const int*)  d_in[0];
    const float* edge_fea = (const float*)d_in[1];
    const int*   idx1     = (const int*)  d_in[2];
    const int*   idx2     = (const int*)  d_in[3];
    const int*   idx3     = (const int*)  d_in[4];
    const float* emb      = (const float*)d_in[5];
    const float* Wf       = (const float*)d_in[6];
    const float* bf       = (const float*)d_in[7];
    const float* g1       = (const float*)d_in[8];
    const float* be1      = (const float*)d_in[9];
    const float* g2       = (const float*)d_in[10];
    const float* be2      = (const float*)d_in[11];
    const float* Wc       = (const float*)d_in[12];
    const float* bc       = (const float*)d_in[13];
    const float* Wo       = (const float*)d_in[14];
    const float* bo       = (const float*)d_in[15];
    float* out = (float*)d_out;

    cudaFuncSetAttribute(k_passA, cudaFuncAttributeMaxDynamicSharedMemorySize, SMEM_A);
    const int SMEM_P = (64 * 256 + 64 * 65) * 4;
    cudaFuncSetAttribute(k_nodeP, cudaFuncAttributeMaxDynamicSharedMemorySize, SMEM_P);

    void *p_cnt1, *p_cntc, *p_stats, *p_nstats, *p_nodeacc, *p_crys;
    cudaGetSymbolAddress(&p_cnt1, g_cnt1);
    cudaGetSymbolAddress(&p_cntc, g_cntc);
    cudaGetSymbolAddress(&p_stats, g_stats);
    cudaGetSymbolAddress(&p_nstats, g_nstats);
    cudaGetSymbolAddress(&p_nodeacc, g_nodeacc);
    cudaGetSymbolAddress(&p_crys, g_crys);

    cudaMemsetAsync(p_cnt1, 0, (size_t)NN * 4);
    cudaMemsetAsync(p_cntc, 0, (size_t)NC * 4);
    k_count_edges<<<(NE + 255) / 256, 256>>>(idx1);
    k_count_crys<<<(NN + 255) / 256, 256>>>(idx3);
    k_inv<<<(NN + 255) / 256, 256>>>();
    k_embed<<<(NN * 16 + 255) / 256, 256>>>(node_fea, emb);

    for (int l = 0; l < NCONV; ++l) {
        cudaMemsetAsync(p_stats, 0, 256 * 4);
        cudaMemsetAsync(p_nstats, 0, 128 * 4);
        cudaMemsetAsync(p_nodeacc, 0, (size_t)NN * NF * 4);
        k_nodeP<<<(NN + 63) / 64, 256, SMEM_P>>>(Wf + (size_t)l * KD * HD);
        k_passA<<<GRID_A, 256, SMEM_A>>>(edge_fea, idx1, idx2,
                                         Wf + (size_t)l * KD * HD, bf + (size_t)l * HD);
        k_fin_edge<<<1, 128>>>(g1 + (size_t)l * HD, be1 + (size_t)l * HD);
        k_passB<<<1184, 256>>>(idx1);
        k_node_stats<<<592, 256>>>();
        k_fin_node<<<1, 64>>>(g2 + (size_t)l * NF, be2 + (size_t)l * NF);
        k_node_apply<<<(NN * 16 + 255) / 256, 256>>>();
    }

    cudaMemsetAsync(p_crys, 0, (size_t)NC * NF * 4);
    k_crys_scatter<<<(NN * 16 + 255) / 256, 256>>>(idx3);
    k_head<<<NC, 128>>>(Wc, bc, Wo, bo, out);
}